// round 1
// baseline (speedup 1.0000x reference)
#include <cuda_runtime.h>
#include <math.h>

#define B  16
#define CIN1 256
#define COUT 128
#define H  128
#define W  128

// Scratch (device globals; no allocation).
__device__ float g_up  [(size_t)B * COUT * H * W];
__device__ float g_down[(size_t)B * COUT * H * W];

// ---------------------------------------------------------------------------
// Direct 3x3 conv (pad 1, stride 1) + BN (+ optional ReLU).
// Block: 256 threads. Tile: 64 co x 8 h x 16 w. ci streamed in chunks of 8.
// Thread: 8 co x 4 w accumulators (one h row).
// ---------------------------------------------------------------------------
template <int CIN, bool RELU>
__global__ __launch_bounds__(256, 2)
void conv3x3_bn(const float* __restrict__ x,
                const float* __restrict__ wgt,
                const float* __restrict__ gamma,
                const float* __restrict__ beta,
                const float* __restrict__ mean,
                const float* __restrict__ var,
                float* __restrict__ out)
{
    constexpr int CC = 8;      // ci chunk
    constexpr int TH = 8;
    constexpr int TW = 16;
    constexpr int CO_BLK = 64;

    __shared__ float xs[CC][TH + 2][TW + 3];   // +3: pad row to 19 to soften conflicts
    __shared__ float ws[CO_BLK][CC][9];

    const int tid = threadIdx.x;
    const int b   = blockIdx.z;
    const int co0 = blockIdx.y * CO_BLK;
    const int wt  = blockIdx.x & 7;        // W/TW = 8
    const int ht  = blockIdx.x >> 3;       // H/TH = 16
    const int h0  = ht * TH;
    const int w0  = wt * TW;

    const int co_g = tid >> 5;             // 0..7  (warp id)
    const int s    = tid & 31;
    const int wq   = s & 3;                // 0..3 -> 4 w's each
    const int hh   = s >> 2;               // 0..7

    float acc[8][4];
#pragma unroll
    for (int i = 0; i < 8; i++)
#pragma unroll
        for (int j = 0; j < 4; j++) acc[i][j] = 0.f;

    for (int ci0 = 0; ci0 < CIN; ci0 += CC) {
        __syncthreads();
        // ---- stage x patch: CC x (TH+2) x (TW+2) ----
        for (int idx = tid; idx < CC * (TH + 2) * (TW + 2); idx += 256) {
            int ci  = idx / ((TH + 2) * (TW + 2));
            int rem = idx % ((TH + 2) * (TW + 2));
            int ph  = rem / (TW + 2);
            int pw  = rem % (TW + 2);
            int gh  = h0 - 1 + ph;
            int gw  = w0 - 1 + pw;
            float v = 0.f;
            if (gh >= 0 && gh < H && gw >= 0 && gw < W)
                v = x[(((size_t)b * CIN + (ci0 + ci)) * H + gh) * W + gw];
            xs[ci][ph][pw] = v;
        }
        // ---- stage weights: CO_BLK x CC x 9 ----
        for (int idx = tid; idx < CO_BLK * CC * 9; idx += 256) {
            int co  = idx / (CC * 9);
            int rem = idx % (CC * 9);
            int ci  = rem / 9;
            int k   = rem % 9;
            ws[co][ci][k] = wgt[(((size_t)(co0 + co)) * CIN + (ci0 + ci)) * 9 + k];
        }
        __syncthreads();

#pragma unroll
        for (int ci = 0; ci < CC; ci++) {
            float xr[3][6];
#pragma unroll
            for (int dh = 0; dh < 3; dh++)
#pragma unroll
                for (int dw = 0; dw < 6; dw++)
                    xr[dh][dw] = xs[ci][hh + dh][wq * 4 + dw];
#pragma unroll
            for (int co = 0; co < 8; co++) {
#pragma unroll
                for (int kh = 0; kh < 3; kh++)
#pragma unroll
                    for (int kw = 0; kw < 3; kw++) {
                        float wv = ws[co_g * 8 + co][ci][kh * 3 + kw];
#pragma unroll
                        for (int j = 0; j < 4; j++)
                            acc[co][j] = fmaf(wv, xr[kh][j + kw], acc[co][j]);
                    }
            }
        }
    }

    // ---- epilogue: BN (+ReLU) ----
    const int h = h0 + hh;
#pragma unroll
    for (int co = 0; co < 8; co++) {
        int c = co0 + co_g * 8 + co;
        float inv = gamma[c] * rsqrtf(var[c] + 1e-5f);
        float bia = beta[c] - mean[c] * inv;
#pragma unroll
        for (int j = 0; j < 4; j++) {
            float v = acc[co][j] * inv + bia;
            if (RELU) v = fmaxf(v, 0.f);
            out[(((size_t)b * COUT + c) * H + h) * W + (w0 + wq * 4 + j)] = v;
        }
    }
}

// ---------------------------------------------------------------------------
// TopPool (reverse cummax over H) fused with the elementwise add:
//   merge[h] = (max_{j>=h} up[j]) + down[h]
// One thread per (b, c, w) column; coalesced across w.
// ---------------------------------------------------------------------------
__global__ void toppool_add(const float* __restrict__ up,
                            const float* __restrict__ down,
                            float* __restrict__ merge)
{
    int idx = blockIdx.x * blockDim.x + threadIdx.x;   // B*COUT*W threads
    if (idx >= B * COUT * W) return;
    int w  = idx % W;
    int bc = idx / W;
    const float* u = up   + (size_t)bc * H * W + w;
    const float* d = down + (size_t)bc * H * W + w;
    float*       m = merge + (size_t)bc * H * W + w;
    float run = -INFINITY;
#pragma unroll 4
    for (int h = H - 1; h >= 0; h--) {
        run = fmaxf(run, u[(size_t)h * W]);
        m[(size_t)h * W] = run + d[(size_t)h * W];
    }
}

// ---------------------------------------------------------------------------
// LeftPool (reverse cummax over W). One block of 128 threads per row,
// Hillis-Steele reverse max-scan in shared memory.
// ---------------------------------------------------------------------------
__global__ void leftpool(const float* __restrict__ in, float* __restrict__ out)
{
    __shared__ float s[W];
    size_t base = (size_t)blockIdx.x * W;   // B*COUT*H rows
    int w = threadIdx.x;
    float v = in[base + w];
    s[w] = v;
    __syncthreads();
#pragma unroll
    for (int off = 1; off < W; off <<= 1) {
        float other = (w + off < W) ? s[w + off] : -INFINITY;
        __syncthreads();
        v = fmaxf(v, other);
        s[w] = v;
        __syncthreads();
    }
    out[base + w] = v;
}

// ---------------------------------------------------------------------------
extern "C" void kernel_launch(void* const* d_in, const int* in_sizes, int n_in,
                              void* d_out, int out_size)
{
    const float* x        = (const float*)d_in[0];
    const float* w_up     = (const float*)d_in[1];
    const float* up_g     = (const float*)d_in[2];
    const float* up_b     = (const float*)d_in[3];
    const float* up_m     = (const float*)d_in[4];
    const float* up_v     = (const float*)d_in[5];
    const float* w_down   = (const float*)d_in[6];
    const float* dn_g     = (const float*)d_in[7];
    const float* dn_b     = (const float*)d_in[8];
    const float* dn_m     = (const float*)d_in[9];
    const float* dn_v     = (const float*)d_in[10];
    const float* w_p      = (const float*)d_in[11];
    const float* p_g      = (const float*)d_in[12];
    const float* p_b      = (const float*)d_in[13];
    const float* p_m      = (const float*)d_in[14];
    const float* p_v      = (const float*)d_in[15];
    float* outp = (float*)d_out;

    float *up_ptr, *down_ptr;
    cudaGetSymbolAddress((void**)&up_ptr,   g_up);
    cudaGetSymbolAddress((void**)&down_ptr, g_down);

    dim3 cgrid(128, COUT / 64, B);   // (h_tiles*w_tiles, co_tiles, batch)

    // conv1: up = relu(bn(conv(x, w_up)))
    conv3x3_bn<CIN1, true><<<cgrid, 256>>>(x, w_up, up_g, up_b, up_m, up_v, up_ptr);
    // conv2: down = relu(bn(conv(x, w_down)))
    conv3x3_bn<CIN1, true><<<cgrid, 256>>>(x, w_down, dn_g, dn_b, dn_m, dn_v, down_ptr);
    // merge = toppool(up) + down  (written over down buffer)
    {
        int total = B * COUT * W;
        toppool_add<<<(total + 255) / 256, 256>>>(up_ptr, down_ptr, down_ptr);
    }
    // conv3: bn(conv(merge, w_p)) -> reuse up buffer
    conv3x3_bn<COUT, false><<<cgrid, 256>>>(down_ptr, w_p, p_g, p_b, p_m, p_v, up_ptr);
    // leftpool -> output
    leftpool<<<B * COUT * H, W>>>(up_ptr, outp);
}

// round 2
// speedup vs baseline: 1.0004x; 1.0004x over previous
#include <cuda_runtime.h>
#include <math.h>

#define B  16
#define CIN1 256
#define COUT 128
#define H  128
#define W  128

// Scratch (device globals; no allocation).
__device__ float g_up  [(size_t)B * COUT * H * W];
__device__ float g_down[(size_t)B * COUT * H * W];

// ---------------------------------------------------------------------------
// Direct 3x3 conv (pad 1, stride 1) + BN (+ optional ReLU).
// Block: 256 threads. Tile: 64 co x 8 h x 16 w. ci streamed in chunks of 8.
// Thread: 8 co x 4 w accumulators (one h row).
// ---------------------------------------------------------------------------
template <int CIN, bool RELU>
__global__ __launch_bounds__(256, 2)
void conv3x3_bn(const float* __restrict__ x,
                const float* __restrict__ wgt,
                const float* __restrict__ gamma,
                const float* __restrict__ beta,
                const float* __restrict__ mean,
                const float* __restrict__ var,
                float* __restrict__ out)
{
    constexpr int CC = 8;      // ci chunk
    constexpr int TH = 8;
    constexpr int TW = 16;
    constexpr int CO_BLK = 64;

    __shared__ float xs[CC][TH + 2][TW + 3];   // +3: pad row to 19 to soften conflicts
    __shared__ float ws[CO_BLK][CC][9];

    const int tid = threadIdx.x;
    const int b   = blockIdx.z;
    const int co0 = blockIdx.y * CO_BLK;
    const int wt  = blockIdx.x & 7;        // W/TW = 8
    const int ht  = blockIdx.x >> 3;       // H/TH = 16
    const int h0  = ht * TH;
    const int w0  = wt * TW;

    const int co_g = tid >> 5;             // 0..7  (warp id)
    const int s    = tid & 31;
    const int wq   = s & 3;                // 0..3 -> 4 w's each
    const int hh   = s >> 2;               // 0..7

    float acc[8][4];
#pragma unroll
    for (int i = 0; i < 8; i++)
#pragma unroll
        for (int j = 0; j < 4; j++) acc[i][j] = 0.f;

    for (int ci0 = 0; ci0 < CIN; ci0 += CC) {
        __syncthreads();
        // ---- stage x patch: CC x (TH+2) x (TW+2) ----
        for (int idx = tid; idx < CC * (TH + 2) * (TW + 2); idx += 256) {
            int ci  = idx / ((TH + 2) * (TW + 2));
            int rem = idx % ((TH + 2) * (TW + 2));
            int ph  = rem / (TW + 2);
            int pw  = rem % (TW + 2);
            int gh  = h0 - 1 + ph;
            int gw  = w0 - 1 + pw;
            float v = 0.f;
            if (gh >= 0 && gh < H && gw >= 0 && gw < W)
                v = x[(((size_t)b * CIN + (ci0 + ci)) * H + gh) * W + gw];
            xs[ci][ph][pw] = v;
        }
        // ---- stage weights: CO_BLK x CC x 9 ----
        for (int idx = tid; idx < CO_BLK * CC * 9; idx += 256) {
            int co  = idx / (CC * 9);
            int rem = idx % (CC * 9);
            int ci  = rem / 9;
            int k   = rem % 9;
            ws[co][ci][k] = wgt[(((size_t)(co0 + co)) * CIN + (ci0 + ci)) * 9 + k];
        }
        __syncthreads();

#pragma unroll
        for (int ci = 0; ci < CC; ci++) {
            float xr[3][6];
#pragma unroll
            for (int dh = 0; dh < 3; dh++)
#pragma unroll
                for (int dw = 0; dw < 6; dw++)
                    xr[dh][dw] = xs[ci][hh + dh][wq * 4 + dw];
#pragma unroll
            for (int co = 0; co < 8; co++) {
#pragma unroll
                for (int kh = 0; kh < 3; kh++)
#pragma unroll
                    for (int kw = 0; kw < 3; kw++) {
                        float wv = ws[co_g * 8 + co][ci][kh * 3 + kw];
#pragma unroll
                        for (int j = 0; j < 4; j++)
                            acc[co][j] = fmaf(wv, xr[kh][j + kw], acc[co][j]);
                    }
            }
        }
    }

    // ---- epilogue: BN (+ReLU) ----
    const int h = h0 + hh;
#pragma unroll
    for (int co = 0; co < 8; co++) {
        int c = co0 + co_g * 8 + co;
        float inv = gamma[c] * rsqrtf(var[c] + 1e-5f);
        float bia = beta[c] - mean[c] * inv;
#pragma unroll
        for (int j = 0; j < 4; j++) {
            float v = acc[co][j] * inv + bia;
            if (RELU) v = fmaxf(v, 0.f);
            out[(((size_t)b * COUT + c) * H + h) * W + (w0 + wq * 4 + j)] = v;
        }
    }
}

// ---------------------------------------------------------------------------
// TopPool (reverse cummax over H) fused with the elementwise add:
//   merge[h] = (max_{j>=h} up[j]) + down[h]
// One thread per (b, c, w) column; coalesced across w.
// ---------------------------------------------------------------------------
__global__ void toppool_add(const float* __restrict__ up,
                            const float* __restrict__ down,
                            float* __restrict__ merge)
{
    int idx = blockIdx.x * blockDim.x + threadIdx.x;   // B*COUT*W threads
    if (idx >= B * COUT * W) return;
    int w  = idx % W;
    int bc = idx / W;
    const float* u = up   + (size_t)bc * H * W + w;
    const float* d = down + (size_t)bc * H * W + w;
    float*       m = merge + (size_t)bc * H * W + w;
    float run = -INFINITY;
#pragma unroll 4
    for (int h = H - 1; h >= 0; h--) {
        run = fmaxf(run, u[(size_t)h * W]);
        m[(size_t)h * W] = run + d[(size_t)h * W];
    }
}

// ---------------------------------------------------------------------------
// LeftPool (reverse cummax over W). One block of 128 threads per row,
// Hillis-Steele reverse max-scan in shared memory.
// ---------------------------------------------------------------------------
__global__ void leftpool(const float* __restrict__ in, float* __restrict__ out)
{
    __shared__ float s[W];
    size_t base = (size_t)blockIdx.x * W;   // B*COUT*H rows
    int w = threadIdx.x;
    float v = in[base + w];
    s[w] = v;
    __syncthreads();
#pragma unroll
    for (int off = 1; off < W; off <<= 1) {
        float other = (w + off < W) ? s[w + off] : -INFINITY;
        __syncthreads();
        v = fmaxf(v, other);
        s[w] = v;
        __syncthreads();
    }
    out[base + w] = v;
}

// ---------------------------------------------------------------------------
extern "C" void kernel_launch(void* const* d_in, const int* in_sizes, int n_in,
                              void* d_out, int out_size)
{
    const float* x        = (const float*)d_in[0];
    const float* w_up     = (const float*)d_in[1];
    const float* up_g     = (const float*)d_in[2];
    const float* up_b     = (const float*)d_in[3];
    const float* up_m     = (const float*)d_in[4];
    const float* up_v     = (const float*)d_in[5];
    const float* w_down   = (const float*)d_in[6];
    const float* dn_g     = (const float*)d_in[7];
    const float* dn_b     = (const float*)d_in[8];
    const float* dn_m     = (const float*)d_in[9];
    const float* dn_v     = (const float*)d_in[10];
    const float* w_p      = (const float*)d_in[11];
    const float* p_g      = (const float*)d_in[12];
    const float* p_b      = (const float*)d_in[13];
    const float* p_m      = (const float*)d_in[14];
    const float* p_v      = (const float*)d_in[15];
    float* outp = (float*)d_out;

    float *up_ptr, *down_ptr;
    cudaGetSymbolAddress((void**)&up_ptr,   g_up);
    cudaGetSymbolAddress((void**)&down_ptr, g_down);

    dim3 cgrid(128, COUT / 64, B);   // (h_tiles*w_tiles, co_tiles, batch)

    // conv1: up = relu(bn(conv(x, w_up)))
    conv3x3_bn<CIN1, true><<<cgrid, 256>>>(x, w_up, up_g, up_b, up_m, up_v, up_ptr);
    // conv2: down = relu(bn(conv(x, w_down)))
    conv3x3_bn<CIN1, true><<<cgrid, 256>>>(x, w_down, dn_g, dn_b, dn_m, dn_v, down_ptr);
    // merge = toppool(up) + down  (written over down buffer)
    {
        int total = B * COUT * W;
        toppool_add<<<(total + 255) / 256, 256>>>(up_ptr, down_ptr, down_ptr);
    }
    // conv3: bn(conv(merge, w_p)) -> reuse up buffer
    conv3x3_bn<COUT, false><<<cgrid, 256>>>(down_ptr, w_p, p_g, p_b, p_m, p_v, up_ptr);
    // leftpool -> output
    leftpool<<<B * COUT * H, W>>>(up_ptr, outp);
}

// round 3
// speedup vs baseline: 2.2391x; 2.2382x over previous
#include <cuda_runtime.h>
#include <math.h>

#define B_   16
#define CIN1 256
#define COUT 128
#define H_   128
#define W_   128

// Scratch (device globals; no allocation).
__device__ float g_up  [(size_t)B_ * COUT * H_ * W_];
__device__ float g_down[(size_t)B_ * COUT * H_ * W_];

__device__ __forceinline__ unsigned f2tf(float f) {
    unsigned r;
    asm("cvt.rna.tf32.f32 %0, %1;" : "=r"(r) : "f"(f));
    return r;
}

__device__ __forceinline__ void mma_tf32(float* c, const unsigned* a, unsigned b0, unsigned b1) {
    asm volatile(
        "mma.sync.aligned.m16n8k8.row.col.f32.tf32.tf32.f32 "
        "{%0,%1,%2,%3},{%4,%5,%6,%7},{%8,%9},{%0,%1,%2,%3};"
        : "+f"(c[0]), "+f"(c[1]), "+f"(c[2]), "+f"(c[3])
        : "r"(a[0]), "r"(a[1]), "r"(a[2]), "r"(a[3]), "r"(b0), "r"(b1));
}

// ---------------------------------------------------------------------------
// tf32 tensor-core implicit-GEMM 3x3 conv (pad 1) + BN (+ReLU).
// Block = 256 threads, tile M=128 co x N=256 px (2 output rows x 128 w).
// K = CIN*9, streamed as ci-chunks of 8 x 9 taps. Warp tile 64x64.
// smem: ws[9][8][136] (conflict-free A), xs[8][4][130] (conflict-free B).
// ---------------------------------------------------------------------------
#define WS_ELEMS (9 * 8 * 136)
#define XS_ELEMS (8 * 4 * 130)
#define SMEM_BYTES ((WS_ELEMS + XS_ELEMS) * 4)

template <int CIN, bool RELU>
__global__ __launch_bounds__(256, 1)
void conv3x3_tf32(const float* __restrict__ x, const float* __restrict__ wgt,
                  const float* __restrict__ gamma, const float* __restrict__ beta,
                  const float* __restrict__ mean, const float* __restrict__ var,
                  float* __restrict__ out)
{
    extern __shared__ unsigned smem[];
    unsigned (*ws)[8][136] = (unsigned(*)[8][136])smem;              // [tap][ci][co pad 136]
    unsigned (*xs)[4][130] = (unsigned(*)[4][130])(smem + WS_ELEMS); // [ci][row][col]

    const int tid  = threadIdx.x;
    const int b    = blockIdx.y;
    const int r0   = blockIdx.x * 2;          // two output rows per block

    const int warp = tid >> 5;
    const int lane = tid & 31;
    const int g    = lane >> 2;               // groupID 0..7
    const int tig  = lane & 3;                // 0..3

    const int mwarp  = warp & 1;              // 2 m-warps (64 co each)
    const int nwarp  = warp >> 1;             // 4 n-warps (64 px each)
    const int rloc   = nwarp >> 1;            // 0/1: which output row
    const int wn0    = (nwarp & 1) * 64;      // w base of warp tile
    const int cobase = mwarp * 64;

    float acc[4][8][4];
#pragma unroll
    for (int mt = 0; mt < 4; mt++)
#pragma unroll
        for (int nt = 0; nt < 8; nt++)
#pragma unroll
            for (int i = 0; i < 4; i++) acc[mt][nt][i] = 0.f;

    for (int ci0 = 0; ci0 < CIN; ci0 += 8) {
        __syncthreads();
        // ---- stage weights: [tap][ci][co], tf32-rounded ----
        for (int idx = tid; idx < COUT * 72; idx += 256) {
            int co  = idx / 72;
            int j   = idx % 72;          // contiguous (ci,tap) run in gmem
            int ci  = j / 9;
            int tap = j % 9;
            ws[tap][ci][co] = f2tf(wgt[((size_t)co * CIN + ci0 + ci) * 9 + tap]);
        }
        // ---- stage x halo tile: 8ci x 4 rows x 130 cols ----
        for (int idx = tid; idx < XS_ELEMS; idx += 256) {
            int ci  = idx / 520;
            int rem = idx % 520;
            int row = rem / 130;
            int col = rem % 130;
            int gh  = r0 - 1 + row;
            int gw  = col - 1;
            float v = 0.f;
            if (gh >= 0 && gh < H_ && gw >= 0 && gw < W_)
                v = x[(((size_t)b * CIN + ci0 + ci) * H_ + gh) * W_ + gw];
            xs[ci][row][col] = f2tf(v);
        }
        __syncthreads();

#pragma unroll
        for (int dh = 0; dh < 3; dh++)
#pragma unroll
            for (int dw = 0; dw < 3; dw++) {
                const int tap = dh * 3 + dw;
                // A fragments: 4 m-tiles of 16 co
                unsigned a[4][4];
#pragma unroll
                for (int mt = 0; mt < 4; mt++) {
                    int cb = cobase + mt * 16 + g;
                    a[mt][0] = ws[tap][tig    ][cb];
                    a[mt][1] = ws[tap][tig    ][cb + 8];
                    a[mt][2] = ws[tap][tig + 4][cb];
                    a[mt][3] = ws[tap][tig + 4][cb + 8];
                }
                const unsigned* p0 = &xs[tig    ][rloc + dh][wn0 + dw + g];
                const unsigned* p1 = &xs[tig + 4][rloc + dh][wn0 + dw + g];
#pragma unroll
                for (int nt = 0; nt < 8; nt++) {
                    unsigned b0 = p0[nt * 8];
                    unsigned b1 = p1[nt * 8];
#pragma unroll
                    for (int mt = 0; mt < 4; mt++)
                        mma_tf32(acc[mt][nt], a[mt], b0, b1);
                }
            }
    }

    // ---- epilogue: BN (+ReLU), float2 stores ----
    const int h = r0 + rloc;
#pragma unroll
    for (int mt = 0; mt < 4; mt++) {
        int c0 = cobase + mt * 16 + g;
        int c1 = c0 + 8;
        float inv0 = gamma[c0] * rsqrtf(var[c0] + 1e-5f);
        float bi0  = beta[c0] - mean[c0] * inv0;
        float inv1 = gamma[c1] * rsqrtf(var[c1] + 1e-5f);
        float bi1  = beta[c1] - mean[c1] * inv1;
        float* o0 = out + (((size_t)b * COUT + c0) * H_ + h) * W_;
        float* o1 = out + (((size_t)b * COUT + c1) * H_ + h) * W_;
#pragma unroll
        for (int nt = 0; nt < 8; nt++) {
            int w = wn0 + nt * 8 + tig * 2;
            float v0 = acc[mt][nt][0] * inv0 + bi0;
            float v1 = acc[mt][nt][1] * inv0 + bi0;
            float v2 = acc[mt][nt][2] * inv1 + bi1;
            float v3 = acc[mt][nt][3] * inv1 + bi1;
            if (RELU) {
                v0 = fmaxf(v0, 0.f); v1 = fmaxf(v1, 0.f);
                v2 = fmaxf(v2, 0.f); v3 = fmaxf(v3, 0.f);
            }
            *(float2*)(o0 + w) = make_float2(v0, v1);
            *(float2*)(o1 + w) = make_float2(v2, v3);
        }
    }
}

// ---------------------------------------------------------------------------
// TopPool (reverse cummax over H) fused with add: merge = cummax_rev(up) + down
// ---------------------------------------------------------------------------
__global__ void toppool_add(const float* __restrict__ up,
                            const float* __restrict__ down,
                            float* __restrict__ merge)
{
    int idx = blockIdx.x * blockDim.x + threadIdx.x;   // B*COUT*W threads
    if (idx >= B_ * COUT * W_) return;
    int w  = idx % W_;
    int bc = idx / W_;
    const float* u = up   + (size_t)bc * H_ * W_ + w;
    const float* d = down + (size_t)bc * H_ * W_ + w;
    float*       m = merge + (size_t)bc * H_ * W_ + w;
    float run = -INFINITY;
#pragma unroll 4
    for (int h = H_ - 1; h >= 0; h--) {
        run = fmaxf(run, u[(size_t)h * W_]);
        m[(size_t)h * W_] = run + d[(size_t)h * W_];
    }
}

// ---------------------------------------------------------------------------
// LeftPool (reverse cummax over W): Hillis-Steele reverse max-scan per row.
// ---------------------------------------------------------------------------
__global__ void leftpool(const float* __restrict__ in, float* __restrict__ out)
{
    __shared__ float s[W_];
    size_t base = (size_t)blockIdx.x * W_;   // B*COUT*H rows
    int w = threadIdx.x;
    float v = in[base + w];
    s[w] = v;
    __syncthreads();
#pragma unroll
    for (int off = 1; off < W_; off <<= 1) {
        float other = (w + off < W_) ? s[w + off] : -INFINITY;
        __syncthreads();
        v = fmaxf(v, other);
        s[w] = v;
        __syncthreads();
    }
    out[base + w] = v;
}

// ---------------------------------------------------------------------------
extern "C" void kernel_launch(void* const* d_in, const int* in_sizes, int n_in,
                              void* d_out, int out_size)
{
    const float* x      = (const float*)d_in[0];
    const float* w_up   = (const float*)d_in[1];
    const float* up_g   = (const float*)d_in[2];
    const float* up_b   = (const float*)d_in[3];
    const float* up_m   = (const float*)d_in[4];
    const float* up_v   = (const float*)d_in[5];
    const float* w_down = (const float*)d_in[6];
    const float* dn_g   = (const float*)d_in[7];
    const float* dn_b   = (const float*)d_in[8];
    const float* dn_m   = (const float*)d_in[9];
    const float* dn_v   = (const float*)d_in[10];
    const float* w_p    = (const float*)d_in[11];
    const float* p_g    = (const float*)d_in[12];
    const float* p_b    = (const float*)d_in[13];
    const float* p_m    = (const float*)d_in[14];
    const float* p_v    = (const float*)d_in[15];
    float* outp = (float*)d_out;

    float *up_ptr, *down_ptr;
    cudaGetSymbolAddress((void**)&up_ptr,   g_up);
    cudaGetSymbolAddress((void**)&down_ptr, g_down);

    // >48KB dynamic smem — raise the opt-in cap (host-side, not a stream op).
    cudaFuncSetAttribute(conv3x3_tf32<CIN1, true>,
                         cudaFuncAttributeMaxDynamicSharedMemorySize, SMEM_BYTES);
    cudaFuncSetAttribute(conv3x3_tf32<COUT, false>,
                         cudaFuncAttributeMaxDynamicSharedMemorySize, SMEM_BYTES);

    dim3 cgrid(H_ / 2, B_);

    // conv1: up = relu(bn(conv(x, w_up)))
    conv3x3_tf32<CIN1, true><<<cgrid, 256, SMEM_BYTES>>>(x, w_up, up_g, up_b, up_m, up_v, up_ptr);
    // conv2: down = relu(bn(conv(x, w_down)))
    conv3x3_tf32<CIN1, true><<<cgrid, 256, SMEM_BYTES>>>(x, w_down, dn_g, dn_b, dn_m, dn_v, down_ptr);
    // merge = toppool(up) + down
    {
        int total = B_ * COUT * W_;
        toppool_add<<<(total + 255) / 256, 256>>>(up_ptr, down_ptr, down_ptr);
    }
    // conv3: bn(conv(merge, w_p))
    conv3x3_tf32<COUT, false><<<cgrid, 256, SMEM_BYTES>>>(down_ptr, w_p, p_g, p_b, p_m, p_v, up_ptr);
    // leftpool -> output
    leftpool<<<B_ * COUT * H_, W_>>>(up_ptr, outp);
}

// round 5
// speedup vs baseline: 4.8484x; 2.1653x over previous
#include <cuda_runtime.h>
#include <math.h>

#define B_   16
#define CIN1 256
#define COUT 128
#define H_   128
#define W_   128

// Scratch (device globals; no allocation).
__device__ float g_up  [(size_t)B_ * COUT * H_ * W_];
__device__ float g_down[(size_t)B_ * COUT * H_ * W_];
__device__ float g_xtf [(size_t)B_ * CIN1 * H_ * W_];   // tf32-rounded x
__device__ float g_wup [9 * CIN1 * COUT];               // packed [tap][ci][co]
__device__ float g_wdn [9 * CIN1 * COUT];
__device__ float g_wp  [9 * COUT * COUT];

__device__ __forceinline__ unsigned f2tf(float f) {
    unsigned r;
    asm("cvt.rna.tf32.f32 %0, %1;" : "=r"(r) : "f"(f));
    return r;
}

__device__ __forceinline__ void mma_tf32(float* c, const unsigned* a, unsigned b0, unsigned b1) {
    asm volatile(
        "mma.sync.aligned.m16n8k8.row.col.f32.tf32.tf32.f32 "
        "{%0,%1,%2,%3},{%4,%5,%6,%7},{%8,%9},{%0,%1,%2,%3};"
        : "+f"(c[0]), "+f"(c[1]), "+f"(c[2]), "+f"(c[3])
        : "r"(a[0]), "r"(a[1]), "r"(a[2]), "r"(a[3]), "r"(b0), "r"(b1));
}

__device__ __forceinline__ void cpa16(unsigned* dst, const float* src, bool pred) {
    unsigned d = (unsigned)__cvta_generic_to_shared(dst);
    int sz = pred ? 16 : 0;
    asm volatile("cp.async.ca.shared.global [%0], [%1], 16, %2;"
                 :: "r"(d), "l"(src), "r"(sz));
}

// smem word layout (double buffered):
//   ws[tap][ci][136]  : 9*8*136  = 9792 words per buffer
//   xs[row][ci][136]  : 4*8*136  = 4352 words per buffer
#define WS_W 9792
#define XS_W 4352
#define BUF_W (WS_W + XS_W)
#define SMEM_BYTES (2 * BUF_W * 4)

// ---------------------------------------------------------------------------
// tf32 tensor-core implicit-GEMM 3x3 conv + BN (+ReLU), cp.async pipelined.
// Block = 256 threads, tile M=128 co x N=256 px (2 rows x 128 w).
// ---------------------------------------------------------------------------
template <int CIN, bool RELU>
__global__ __launch_bounds__(256, 1)
void conv3x3_tf32(const float* __restrict__ xtf, const float* __restrict__ wp,
                  const float* __restrict__ gamma, const float* __restrict__ beta,
                  const float* __restrict__ mean, const float* __restrict__ var,
                  float* __restrict__ out)
{
    extern __shared__ unsigned sm[];
    unsigned* wsb[2] = { sm,          sm + BUF_W          };
    unsigned* xsb[2] = { sm + WS_W,   sm + BUF_W + WS_W   };

    const int tid  = threadIdx.x;
    const int b    = blockIdx.y;
    const int r0   = blockIdx.x * 2;

    const int warp = tid >> 5;
    const int lane = tid & 31;
    const int g    = lane >> 2;
    const int tig  = lane & 3;

    const int mwarp  = warp & 1;
    const int nwarp  = warp >> 1;
    const int rloc   = nwarp >> 1;
    const int wn0    = (nwarp & 1) * 64;
    const int cobase = mwarp * 64;

    // static-zero halo columns (col 3 <- gw=-1, col 132 <- gw=128), both buffers
    if (tid < 128) {
        int bufsel = tid & 1;
        int colsel = (tid >> 1) & 1;
        int ci     = (tid >> 2) & 7;
        int row    = (tid >> 5) & 3;
        xsb[bufsel][row * 1088 + ci * 136 + (colsel ? 132 : 3)] = 0u;
    }

    float acc[4][8][4];
#pragma unroll
    for (int mt = 0; mt < 4; mt++)
#pragma unroll
        for (int nt = 0; nt < 8; nt++)
#pragma unroll
            for (int i = 0; i < 4; i++) acc[mt][nt][i] = 0.f;

    constexpr int NC = CIN / 8;

    // ---- staging (all cp.async 16B) ----
    auto stage = [&](int c, int bufsel) {
        const int ci0 = c * 8;
        unsigned* ws = wsb[bufsel];
        unsigned* xs = xsb[bufsel];
        // weights: 9 taps x 8 ci x 128 co  (2304 x 16B)
#pragma unroll
        for (int k = 0; k < 9; k++) {
            int idx = tid + k * 256;
            int tap = idx >> 8;
            int rem = idx & 255;
            int ci  = rem >> 5;
            int cc  = rem & 31;
            cpa16(ws + tap * 1088 + ci * 136 + cc * 4,
                  wp + ((size_t)tap * CIN + ci0 + ci) * COUT + cc * 4, true);
        }
        // x: 4 rows x 8 ci x 128 cols  (1024 x 16B), zero-fill OOB rows
#pragma unroll
        for (int k = 0; k < 4; k++) {
            int idx = tid + k * 256;
            int row = idx >> 8;
            int rem = idx & 255;
            int ci  = rem >> 5;
            int cc  = rem & 31;
            int gh  = r0 - 1 + row;
            bool ok = (gh >= 0) && (gh < H_);
            cpa16(xs + row * 1088 + ci * 136 + 4 + cc * 4,
                  xtf + (((size_t)b * CIN + ci0 + ci) * H_ + (ok ? gh : 0)) * W_ + cc * 4,
                  ok);
        }
    };

    stage(0, 0);
    asm volatile("cp.async.commit_group;");

    for (int c = 0; c < NC; c++) {
        if (c + 1 < NC) {
            stage(c + 1, (c + 1) & 1);
            asm volatile("cp.async.commit_group;");
            asm volatile("cp.async.wait_group 1;");
        } else {
            asm volatile("cp.async.wait_group 0;");
        }
        __syncthreads();

        const unsigned* ws = wsb[c & 1];
        const unsigned* xs = xsb[c & 1];

#pragma unroll
        for (int dh = 0; dh < 3; dh++)
#pragma unroll
            for (int dw = 0; dw < 3; dw++) {
                const int tap = dh * 3 + dw;
                const unsigned* wr0 = ws + tap * 1088 + tig * 136;
                const unsigned* wr1 = wr0 + 4 * 136;
                unsigned a[4][4];
#pragma unroll
                for (int mt = 0; mt < 4; mt++) {
                    int cb = cobase + mt * 16 + g;
                    a[mt][0] = wr0[cb];
                    a[mt][1] = wr0[cb + 8];
                    a[mt][2] = wr1[cb];
                    a[mt][3] = wr1[cb + 8];
                }
                const unsigned* p0 = xs + (rloc + dh) * 1088 + tig * 136
                                        + wn0 + g + dw + 3;
                const unsigned* p1 = p0 + 4 * 136;
#pragma unroll
                for (int nt = 0; nt < 8; nt++) {
                    unsigned b0 = p0[nt * 8];
                    unsigned b1 = p1[nt * 8];
#pragma unroll
                    for (int mt = 0; mt < 4; mt++)
                        mma_tf32(acc[mt][nt], a[mt], b0, b1);
                }
            }
        __syncthreads();   // buffer reuse fence for stage(c+2)
    }

    // ---- epilogue: BN (+ReLU), float2 stores ----
    const int h = r0 + rloc;
#pragma unroll
    for (int mt = 0; mt < 4; mt++) {
        int c0 = cobase + mt * 16 + g;
        int c1 = c0 + 8;
        float inv0 = gamma[c0] * rsqrtf(var[c0] + 1e-5f);
        float bi0  = beta[c0] - mean[c0] * inv0;
        float inv1 = gamma[c1] * rsqrtf(var[c1] + 1e-5f);
        float bi1  = beta[c1] - mean[c1] * inv1;
        float* o0 = out + (((size_t)b * COUT + c0) * H_ + h) * W_;
        float* o1 = out + (((size_t)b * COUT + c1) * H_ + h) * W_;
#pragma unroll
        for (int nt = 0; nt < 8; nt++) {
            int w = wn0 + nt * 8 + tig * 2;
            float v0 = acc[mt][nt][0] * inv0 + bi0;
            float v1 = acc[mt][nt][1] * inv0 + bi0;
            float v2 = acc[mt][nt][2] * inv1 + bi1;
            float v3 = acc[mt][nt][3] * inv1 + bi1;
            if (RELU) {
                v0 = fmaxf(v0, 0.f); v1 = fmaxf(v1, 0.f);
                v2 = fmaxf(v2, 0.f); v3 = fmaxf(v3, 0.f);
            }
            *(float2*)(o0 + w) = make_float2(v0, v1);
            *(float2*)(o1 + w) = make_float2(v2, v3);
        }
    }
}

// ---------------------------------------------------------------------------
// Prep: round x to tf32 bits (vectorized).
// ---------------------------------------------------------------------------
__global__ void round_x(const float* __restrict__ x, float* __restrict__ xt, size_t n4)
{
    size_t i = (size_t)blockIdx.x * blockDim.x + threadIdx.x;
    if (i >= n4) return;
    float4 v = ((const float4*)x)[i];
    v.x = __uint_as_float(f2tf(v.x));
    v.y = __uint_as_float(f2tf(v.y));
    v.z = __uint_as_float(f2tf(v.z));
    v.w = __uint_as_float(f2tf(v.w));
    ((float4*)xt)[i] = v;
}

// Prep: pack weights [co][ci][3][3] -> tf32 [tap][ci][co].
template <int CIN>
__global__ void pack_w(const float* __restrict__ w, float* __restrict__ wp)
{
    int idx = blockIdx.x * blockDim.x + threadIdx.x;   // 9*CIN*COUT
    if (idx >= 9 * CIN * COUT) return;
    int co  = idx & (COUT - 1);
    int r   = idx / COUT;
    int ci  = r % CIN;
    int tap = r / CIN;
    wp[idx] = __uint_as_float(f2tf(w[((size_t)co * CIN + ci) * 9 + tap]));
}

// ---------------------------------------------------------------------------
// TopPool (reverse cummax over H) + add; emits tf32-rounded merge.
// ---------------------------------------------------------------------------
__global__ void toppool_add(const float* __restrict__ up,
                            const float* __restrict__ down,
                            float* __restrict__ merge)
{
    int idx = blockIdx.x * blockDim.x + threadIdx.x;
    if (idx >= B_ * COUT * W_) return;
    int w  = idx % W_;
    int bc = idx / W_;
    const float* u = up   + (size_t)bc * H_ * W_ + w;
    const float* d = down + (size_t)bc * H_ * W_ + w;
    float*       m = merge + (size_t)bc * H_ * W_ + w;
    float run = -INFINITY;
#pragma unroll 4
    for (int h = H_ - 1; h >= 0; h--) {
        run = fmaxf(run, u[(size_t)h * W_]);
        m[(size_t)h * W_] = __uint_as_float(f2tf(run + d[(size_t)h * W_]));
    }
}

// ---------------------------------------------------------------------------
// LeftPool (reverse cummax over W): Hillis-Steele reverse max-scan per row.
// ---------------------------------------------------------------------------
__global__ void leftpool(const float* __restrict__ in, float* __restrict__ out)
{
    __shared__ float s[W_];
    size_t base = (size_t)blockIdx.x * W_;
    int w = threadIdx.x;
    float v = in[base + w];
    s[w] = v;
    __syncthreads();
#pragma unroll
    for (int off = 1; off < W_; off <<= 1) {
        float other = (w + off < W_) ? s[w + off] : -INFINITY;
        __syncthreads();
        v = fmaxf(v, other);
        s[w] = v;
        __syncthreads();
    }
    out[base + w] = v;
}

// ---------------------------------------------------------------------------
extern "C" void kernel_launch(void* const* d_in, const int* in_sizes, int n_in,
                              void* d_out, int out_size)
{
    const float* x      = (const float*)d_in[0];
    const float* w_up   = (const float*)d_in[1];
    const float* up_g   = (const float*)d_in[2];
    const float* up_b   = (const float*)d_in[3];
    const float* up_m   = (const float*)d_in[4];
    const float* up_v   = (const float*)d_in[5];
    const float* w_down = (const float*)d_in[6];
    const float* dn_g   = (const float*)d_in[7];
    const float* dn_b   = (const float*)d_in[8];
    const float* dn_m   = (const float*)d_in[9];
    const float* dn_v   = (const float*)d_in[10];
    const float* w_p    = (const float*)d_in[11];
    const float* p_g    = (const float*)d_in[12];
    const float* p_b    = (const float*)d_in[13];
    const float* p_m    = (const float*)d_in[14];
    const float* p_v    = (const float*)d_in[15];
    float* outp = (float*)d_out;

    float *up_ptr, *down_ptr, *xtf, *wup, *wdn, *wpp;
    cudaGetSymbolAddress((void**)&up_ptr,   g_up);
    cudaGetSymbolAddress((void**)&down_ptr, g_down);
    cudaGetSymbolAddress((void**)&xtf,      g_xtf);
    cudaGetSymbolAddress((void**)&wup,      g_wup);
    cudaGetSymbolAddress((void**)&wdn,      g_wdn);
    cudaGetSymbolAddress((void**)&wpp,      g_wp);

    cudaFuncSetAttribute(conv3x3_tf32<CIN1, true>,
                         cudaFuncAttributeMaxDynamicSharedMemorySize, SMEM_BYTES);
    cudaFuncSetAttribute(conv3x3_tf32<COUT, false>,
                         cudaFuncAttributeMaxDynamicSharedMemorySize, SMEM_BYTES);

    // ---- prep: tf32-round x, pack+round weights ----
    {
        size_t n4 = (size_t)B_ * CIN1 * H_ * W_ / 4;
        round_x<<<(unsigned)((n4 + 255) / 256), 256>>>(x, xtf, n4);
        int nw = 9 * CIN1 * COUT;
        pack_w<CIN1><<<(nw + 255) / 256, 256>>>(w_up,   wup);
        pack_w<CIN1><<<(nw + 255) / 256, 256>>>(w_down, wdn);
        int np = 9 * COUT * COUT;
        pack_w<COUT><<<(np + 255) / 256, 256>>>(w_p, wpp);
    }

    dim3 cgrid(H_ / 2, B_);
    conv3x3_tf32<CIN1, true><<<cgrid, 256, SMEM_BYTES>>>(xtf, wup, up_g, up_b, up_m, up_v, up_ptr);
    conv3x3_tf32<CIN1, true><<<cgrid, 256, SMEM_BYTES>>>(xtf, wdn, dn_g, dn_b, dn_m, dn_v, down_ptr);
    {
        int total = B_ * COUT * W_;
        toppool_add<<<(total + 255) / 256, 256>>>(up_ptr, down_ptr, down_ptr);
    }
    conv3x3_tf32<COUT, false><<<cgrid, 256, SMEM_BYTES>>>(down_ptr, wpp, p_g, p_b, p_m, p_v, up_ptr);
    leftpool<<<B_ * COUT * H_, W_>>>(up_ptr, outp);
}